// round 9
// baseline (speedup 1.0000x reference)
#include <cuda_runtime.h>

// ---------------------------------------------------------------------------
// Compile-time Clebsch-Gordan coefficients (Racah formula, double precision),
// baked into the fully-unrolled kernel as FFMA immediates.
// ---------------------------------------------------------------------------
namespace cg {

__host__ __device__ constexpr double cfact(int n) {
    double r = 1.0;
    for (int i = 2; i <= n; ++i) r *= (double)i;
    return r;
}

__host__ __device__ constexpr double csqrt(double x) {
    if (x <= 0.0) return 0.0;
    double r = x < 1.0 ? 1.0 : x;
    for (int i = 0; i < 100; ++i) r = 0.5 * (r + x / r);
    return r;
}

__host__ __device__ constexpr double clebsch(int j1, int m1, int j2, int m2, int j, int m) {
    if (m1 + m2 != m) return 0.0;
    double pre = csqrt((2.0 * j + 1.0) * cfact(j + j1 - j2) * cfact(j - j1 + j2) *
                       cfact(j1 + j2 - j) / cfact(j1 + j2 + j + 1));
    pre *= csqrt(cfact(j + m) * cfact(j - m) * cfact(j1 - m1) * cfact(j1 + m1) *
                 cfact(j2 - m2) * cfact(j2 + m2));
    double s = 0.0;
    int vmin = 0;
    if (j2 - j - m1 > vmin) vmin = j2 - j - m1;
    if (j1 + m2 - j > vmin) vmin = j1 + m2 - j;
    int vmax = j1 + j2 - j;
    if (j1 - m1 < vmax) vmax = j1 - m1;
    if (j2 + m2 < vmax) vmax = j2 + m2;
    for (int v = vmin; v <= vmax; ++v) {
        double d = cfact(v) * cfact(j1 + j2 - j - v) * cfact(j1 - m1 - v) *
                   cfact(j2 + m2 - v) * cfact(j - j2 + m1 + v) * cfact(j - j1 - m2 + v);
        s += ((v & 1) ? -1.0 : 1.0) / d;
    }
    return pre * s;
}

}  // namespace cg

// ---------------------------------------------------------------------------
// compile-time for
// ---------------------------------------------------------------------------
template <int V> struct Ic { static constexpr int value = V; };

template <int I, int N, class F>
__device__ __forceinline__ void cfor_(F&& f) {
    if constexpr (I < N) {
        f(Ic<I>{});
        cfor_<I + 1, N>(f);
    }
}
template <int N, class F>
__device__ __forceinline__ void cfor(F&& f) { cfor_<0, N>(f); }

// ---------------------------------------------------------------------------
// 32-byte vector: 4 channels of complex = {re,im} x 4, as two float4s.
// ---------------------------------------------------------------------------
struct F8 { float4 lo, hi; };

__device__ __forceinline__ F8 f8zero() {
    F8 r;
    r.lo = make_float4(0.f, 0.f, 0.f, 0.f);
    r.hi = make_float4(0.f, 0.f, 0.f, 0.f);
    return r;
}

__device__ __forceinline__ F8 f8neg(const F8 v) {
    F8 r;
    r.lo = make_float4(-v.lo.x, -v.lo.y, -v.lo.z, -v.lo.w);
    r.hi = make_float4(-v.hi.x, -v.hi.y, -v.hi.z, -v.hi.w);
    return r;
}

// complex fma on 4 channel pairs: o += c * (u * v)  (complex product per pair)
__device__ __forceinline__ void cfma4(float4& o, float c, const float4 u, const float4 v) {
    o.x += c * (u.x * v.x - u.y * v.y);
    o.y += c * (u.x * v.y + u.y * v.x);
    o.z += c * (u.z * v.z - u.w * v.w);
    o.w += c * (u.z * v.w + u.w * v.z);
}
__device__ __forceinline__ void cfma(F8& o, float c, const F8 u, const F8 v) {
    cfma4(o.lo, c, u.lo, v.lo);
    cfma4(o.hi, c, u.hi, v.hi);
}

// 256-bit store (sm_100a+, PTX 8.7). addr must be 32B aligned.
__device__ __forceinline__ void st8(float4* p, const F8 v) {
    asm volatile(
        "st.global.v8.f32 [%0], {%1, %2, %3, %4, %5, %6, %7, %8};"
        :: "l"((void*)p),
           "f"(v.lo.x), "f"(v.lo.y), "f"(v.lo.z), "f"(v.lo.w),
           "f"(v.hi.x), "f"(v.hi.y), "f"(v.hi.z), "f"(v.hi.w)
        : "memory");
}

// Load one F8 (two read-only float4 loads).
__device__ __forceinline__ F8 ld8(const float4* X, unsigned idx4 /*float4 units*/) {
    F8 r;
    r.lo = __ldg(&X[idx4]);
    r.hi = __ldg(&X[idx4 + 1u]);
    return r;
}

// ---------------------------------------------------------------------------
// General bilinear contraction out[m] = sum_{p,q} C[p,q,m] * A[p] (x) B[q]
// ---------------------------------------------------------------------------
template <int l1, int l2, int l>
__device__ __forceinline__ void contract(const F8* A, const F8* Bv, F8* out) {
    cfor<2 * l + 1>([&](auto M) { out[decltype(M)::value] = f8zero(); });
    cfor<(2 * l1 + 1) * (2 * l2 + 1)>([&](auto PQ) {
        constexpr int pq = decltype(PQ)::value;
        constexpr int p = pq / (2 * l2 + 1);
        constexpr int q = pq % (2 * l2 + 1);
        constexpr int m = (p - l1) + (q - l2);
        if constexpr (m >= -l && m <= l) {
            constexpr float c = (float)cg::clebsch(l1, p - l1, l2, q - l2, l, m);
            if constexpr (c != 0.0f) cfma(out[m + l], c, A[p], Bv[q]);
        }
    });
}

// Self-product with symmetric CG (even 2*l1 - l): fold p<q terms with 2*C.
template <int l1, int l>
__device__ __forceinline__ void contract_sym(const F8* A, F8* out) {
    cfor<2 * l + 1>([&](auto M) { out[decltype(M)::value] = f8zero(); });
    cfor<(2 * l1 + 1) * (2 * l1 + 1)>([&](auto PQ) {
        constexpr int pq = decltype(PQ)::value;
        constexpr int p = pq / (2 * l1 + 1);
        constexpr int q = pq % (2 * l1 + 1);
        if constexpr (q >= p) {
            constexpr int m = (p - l1) + (q - l1);
            if constexpr (m >= -l && m <= l) {
                constexpr double c0 = cg::clebsch(l1, p - l1, l1, q - l1, l, m);
                constexpr float c = (float)((p == q) ? c0 : 2.0 * c0);
                if constexpr (c != 0.0f) cfma(out[m + l], c, A[p], A[q]);
            }
        }
    });
}

// ---------------------------------------------------------------------------
// Kernel. B=1024, T=512. Grid (8, 1024): blockIdx.y = batch b, blockIdx.x =
// piece. 128 threads/CTA; each thread owns 4 channels (one 32B F8), so every
// store is a 256-bit STG (1KB contiguous per warp instruction) -> half the
// LSU store instructions vs STG.128, better DRAM burst locality.
// 8 pieces keep each piece's live registers under 128 (4 CTAs/SM).
//
// Output row = (part l, b, m, slot): T*2 floats = 128 F8. Addressing in F8
// units: base_l + (b*(2l+1)+m)*n_l*128 + slot*128 + t, stored at float4
// index 2x that.
// ---------------------------------------------------------------------------
__global__ void __launch_bounds__(128, 4) cg_kernel(
    const float4* __restrict__ X0, const float4* __restrict__ X1,
    const float4* __restrict__ X2, float4* __restrict__ O) {
    const unsigned piece = blockIdx.x;  // 0..7
    const unsigned b = blockIdx.y;
    const unsigned t = threadIdx.x;     // F8 slot 0..127

    // part bases / strides in F8 units
    const unsigned P0 = (0u        + b * 384u)  + t;  // l=0: n=3
    const unsigned P1 = (393216u   + b * 2304u) + t;  // l=1: n=6, m stride 768
    const unsigned P2 = (2752512u  + b * 3840u) + t;  // l=2: n=6, m stride 768
    const unsigned P3 = (6684672u  + b * 2688u) + t;  // l=3: n=3, m stride 384
    const unsigned P4 = (9437184u  + b * 1152u) + t;  // l=4: n=1, m stride 128

    const F8 Z = f8zero();
    F8 out[9];

    switch (piece) {
    case 0: {  // l=0 part: 3 rows
        F8 a0[1], a1[3], a2[5];
        a0[0] = ld8(X0, b * 256u + 2u * t);
        cfor<3>([&](auto P) { constexpr int p = decltype(P)::value; a1[p] = ld8(X1, (b * 3u + p) * 256u + 2u * t); });
        cfor<5>([&](auto P) { constexpr int p = decltype(P)::value; a2[p] = ld8(X2, (b * 5u + p) * 256u + 2u * t); });
        contract<0, 0, 0>(a0, a0, out);
        st8(&O[2u * (P0 + 0u)], out[0]);
        contract_sym<1, 0>(a1, out);
        st8(&O[2u * (P0 + 128u)], out[0]);
        contract_sym<2, 0>(a2, out);
        st8(&O[2u * (P0 + 256u)], out[0]);
        break;
    }
    case 1: {  // l=1: (0,1,1)@s0, (1,0,1)@s1, zeros @s2,@s5 : 12 rows
        F8 a0[1], a1[3];
        a0[0] = ld8(X0, b * 256u + 2u * t);
        cfor<3>([&](auto P) { constexpr int p = decltype(P)::value; a1[p] = ld8(X1, (b * 3u + p) * 256u + 2u * t); });
        contract<0, 1, 1>(a0, a1, out);
        cfor<3>([&](auto M) {
            constexpr int m = decltype(M)::value;
            st8(&O[2u * (P1 + m * 768u + 0u)],   out[m]);
            st8(&O[2u * (P1 + m * 768u + 128u)], out[m]);
            st8(&O[2u * (P1 + m * 768u + 256u)], Z);
            st8(&O[2u * (P1 + m * 768u + 640u)], Z);
        });
        break;
    }
    case 2: {  // l=1: (1,2,1)@s3, (2,1,1)@s4 : 6 rows
        F8 a1[3], a2[5];
        cfor<3>([&](auto P) { constexpr int p = decltype(P)::value; a1[p] = ld8(X1, (b * 3u + p) * 256u + 2u * t); });
        cfor<5>([&](auto P) { constexpr int p = decltype(P)::value; a2[p] = ld8(X2, (b * 5u + p) * 256u + 2u * t); });
        contract<1, 2, 1>(a1, a2, out);
        cfor<3>([&](auto M) {
            constexpr int m = decltype(M)::value;
            st8(&O[2u * (P1 + m * 768u + 384u)], out[m]);
            st8(&O[2u * (P1 + m * 768u + 512u)], out[m]);
        });
        break;
    }
    case 3: {  // l=2: (0,2,2)@s0, (2,0,2)@s3 : 10 rows
        F8 a0[1], a2[5];
        a0[0] = ld8(X0, b * 256u + 2u * t);
        cfor<5>([&](auto P) { constexpr int p = decltype(P)::value; a2[p] = ld8(X2, (b * 5u + p) * 256u + 2u * t); });
        contract<0, 2, 2>(a0, a2, out);
        cfor<5>([&](auto M) {
            constexpr int m = decltype(M)::value;
            st8(&O[2u * (P2 + m * 768u + 0u)],   out[m]);
            st8(&O[2u * (P2 + m * 768u + 384u)], out[m]);
        });
        break;
    }
    case 4: {  // l=2: (1,1,2)@s1, (2,2,2)@s5 : 10 rows
        F8 a1[3], a2[5];
        cfor<3>([&](auto P) { constexpr int p = decltype(P)::value; a1[p] = ld8(X1, (b * 3u + p) * 256u + 2u * t); });
        cfor<5>([&](auto P) { constexpr int p = decltype(P)::value; a2[p] = ld8(X2, (b * 5u + p) * 256u + 2u * t); });
        contract_sym<1, 2>(a1, out);
        cfor<5>([&](auto M) {
            constexpr int m = decltype(M)::value;
            st8(&O[2u * (P2 + m * 768u + 128u)], out[m]);
        });
        contract_sym<2, 2>(a2, out);
        cfor<5>([&](auto M) {
            constexpr int m = decltype(M)::value;
            st8(&O[2u * (P2 + m * 768u + 640u)], out[m]);
        });
        break;
    }
    case 5: {  // l=2: (1,2,2)@s2, (2,1,2)@s4 = -(1,2,2) : 10 rows
        F8 a1[3], a2[5];
        cfor<3>([&](auto P) { constexpr int p = decltype(P)::value; a1[p] = ld8(X1, (b * 3u + p) * 256u + 2u * t); });
        cfor<5>([&](auto P) { constexpr int p = decltype(P)::value; a2[p] = ld8(X2, (b * 5u + p) * 256u + 2u * t); });
        contract<1, 2, 2>(a1, a2, out);
        cfor<5>([&](auto M) {
            constexpr int m = decltype(M)::value;
            st8(&O[2u * (P2 + m * 768u + 256u)], out[m]);
            st8(&O[2u * (P2 + m * 768u + 512u)], f8neg(out[m]));
        });
        break;
    }
    case 6: {  // l=3: (1,2,3)@s0, (2,1,3)@s1, zeros @s2 : 21 rows
        F8 a1[3], a2[5];
        cfor<3>([&](auto P) { constexpr int p = decltype(P)::value; a1[p] = ld8(X1, (b * 3u + p) * 256u + 2u * t); });
        cfor<5>([&](auto P) { constexpr int p = decltype(P)::value; a2[p] = ld8(X2, (b * 5u + p) * 256u + 2u * t); });
        contract<1, 2, 3>(a1, a2, out);
        cfor<7>([&](auto M) {
            constexpr int m = decltype(M)::value;
            st8(&O[2u * (P3 + m * 384u + 0u)],   out[m]);
            st8(&O[2u * (P3 + m * 384u + 128u)], out[m]);
            st8(&O[2u * (P3 + m * 384u + 256u)], Z);
        });
        break;
    }
    default: {  // piece 7: l=4 part, 9 rows
        F8 a2[5];
        cfor<5>([&](auto P) { constexpr int p = decltype(P)::value; a2[p] = ld8(X2, (b * 5u + p) * 256u + 2u * t); });
        contract_sym<2, 4>(a2, out);
        cfor<9>([&](auto M) {
            constexpr int m = decltype(M)::value;
            st8(&O[2u * (P4 + m * 128u)], out[m]);
        });
        break;
    }
    }
}

// ---------------------------------------------------------------------------
extern "C" void kernel_launch(void* const* d_in, const int* in_sizes, int n_in,
                              void* d_out, int out_size) {
    // Identify inputs by element count (robust to metadata ordering).
    const float* x0 = (const float*)d_in[0];
    const float* x1 = n_in > 1 ? (const float*)d_in[1] : nullptr;
    const float* x2 = n_in > 2 ? (const float*)d_in[2] : nullptr;
    for (int i = 0; i < n_in; ++i) {
        if (in_sizes[i] == 1024 * 1 * 512 * 2) x0 = (const float*)d_in[i];
        else if (in_sizes[i] == 1024 * 3 * 512 * 2) x1 = (const float*)d_in[i];
        else if (in_sizes[i] == 1024 * 5 * 512 * 2) x2 = (const float*)d_in[i];
    }
    dim3 grid(8, 1024);
    cg_kernel<<<grid, 128>>>((const float4*)x0, (const float4*)x1,
                             (const float4*)x2, (float4*)d_out);
}